// round 1
// baseline (speedup 1.0000x reference)
#include <cuda_runtime.h>
#include <math.h>

#define BSZ 4
#define TLEN 2048
#define CDIM 1024
#define NH 16
#define HD 64
#define BT (BSZ * TLEN)      /* 8192 */
#define N3 (3 * CDIM)        /* 3072 */

// Scratch (allocation-free rule: __device__ globals)
__device__ float g_Q[BT * CDIM];    // [B,H,T,Dh]
__device__ float g_K[BT * CDIM];
__device__ float g_V[BT * CDIM];
__device__ float g_att[BT * CDIM];  // [B,T,C]

// ---------------------------------------------------------------------------
// GEMM 1: qkv = x @ W_qkv + b_qkv, scattered directly into Q/K/V [B,H,T,Dh]
// 128x128 block tile, 8x8 per-thread, BK=8, 256 threads.
// ---------------------------------------------------------------------------
#define GBM 128
#define GBN 128
#define GBK 8

__global__ __launch_bounds__(256) void qkv_gemm(const float* __restrict__ A,
                                                const float* __restrict__ W,
                                                const float* __restrict__ bias) {
    __shared__ float As[GBK][GBM];
    __shared__ float Bs[GBK][GBN];
    const int t = threadIdx.x;
    const int m0 = blockIdx.y * GBM;
    const int n0 = blockIdx.x * GBN;
    const int ty = t >> 4, tx = t & 15;

    float acc[8][8];
#pragma unroll
    for (int i = 0; i < 8; i++)
#pragma unroll
        for (int j = 0; j < 8; j++) acc[i][j] = 0.f;

    const int arow = t >> 1, ac4 = (t & 1) * 4;
    const int brow = t >> 5, bc4 = (t & 31) * 4;
    const float* Aptr = A + (size_t)(m0 + arow) * CDIM + ac4;
    const float* Wptr = W + (size_t)brow * N3 + n0 + bc4;

    for (int k0 = 0; k0 < CDIM; k0 += GBK) {
        float4 av = *(const float4*)(Aptr + k0);
        float4 bv = *(const float4*)(Wptr + (size_t)k0 * N3);
        As[ac4 + 0][arow] = av.x;
        As[ac4 + 1][arow] = av.y;
        As[ac4 + 2][arow] = av.z;
        As[ac4 + 3][arow] = av.w;
        *(float4*)&Bs[brow][bc4] = bv;
        __syncthreads();
#pragma unroll
        for (int k = 0; k < GBK; k++) {
            float a[8], b[8];
#pragma unroll
            for (int i = 0; i < 8; i++) a[i] = As[k][ty * 8 + i];
#pragma unroll
            for (int j = 0; j < 8; j++) b[j] = Bs[k][tx * 8 + j];
#pragma unroll
            for (int i = 0; i < 8; i++)
#pragma unroll
                for (int j = 0; j < 8; j++) acc[i][j] += a[i] * b[j];
        }
        __syncthreads();
    }

    // Epilogue: scatter to Q/K/V in [B,H,T,Dh].
    // 8-wide n chunks never cross a 64 (head) boundary, nor a 1024 (which) one.
    const int gn_base = n0 + tx * 8;
    const int which = gn_base >> 10;
    const int c = gn_base & 1023;
    const int h = c >> 6, d0 = c & 63;
    float* dst = (which == 0) ? g_Q : ((which == 1) ? g_K : g_V);
#pragma unroll
    for (int i = 0; i < 8; i++) {
        const int gm = m0 + ty * 8 + i;
        const int b = gm >> 11, tt = gm & 2047;
        float* row = dst + ((size_t)(b * NH + h) * TLEN + tt) * HD + d0;
#pragma unroll
        for (int j = 0; j < 8; j++) {
            row[j] = acc[i][j] + bias[gn_base + j];
        }
    }
}

// ---------------------------------------------------------------------------
// GEMM 2: out = attn @ W_proj + b_proj    (M=8192, N=1024, K=1024)
// ---------------------------------------------------------------------------
__global__ __launch_bounds__(256) void proj_gemm(const float* __restrict__ A,
                                                 const float* __restrict__ W,
                                                 const float* __restrict__ bias,
                                                 float* __restrict__ out) {
    __shared__ float As[GBK][GBM];
    __shared__ float Bs[GBK][GBN];
    const int t = threadIdx.x;
    const int m0 = blockIdx.y * GBM;
    const int n0 = blockIdx.x * GBN;
    const int ty = t >> 4, tx = t & 15;

    float acc[8][8];
#pragma unroll
    for (int i = 0; i < 8; i++)
#pragma unroll
        for (int j = 0; j < 8; j++) acc[i][j] = 0.f;

    const int arow = t >> 1, ac4 = (t & 1) * 4;
    const int brow = t >> 5, bc4 = (t & 31) * 4;
    const float* Aptr = A + (size_t)(m0 + arow) * CDIM + ac4;
    const float* Wptr = W + (size_t)brow * CDIM + n0 + bc4;

    for (int k0 = 0; k0 < CDIM; k0 += GBK) {
        float4 av = *(const float4*)(Aptr + k0);
        float4 bv = *(const float4*)(Wptr + (size_t)k0 * CDIM);
        As[ac4 + 0][arow] = av.x;
        As[ac4 + 1][arow] = av.y;
        As[ac4 + 2][arow] = av.z;
        As[ac4 + 3][arow] = av.w;
        *(float4*)&Bs[brow][bc4] = bv;
        __syncthreads();
#pragma unroll
        for (int k = 0; k < GBK; k++) {
            float a[8], b[8];
#pragma unroll
            for (int i = 0; i < 8; i++) a[i] = As[k][ty * 8 + i];
#pragma unroll
            for (int j = 0; j < 8; j++) b[j] = Bs[k][tx * 8 + j];
#pragma unroll
            for (int i = 0; i < 8; i++)
#pragma unroll
                for (int j = 0; j < 8; j++) acc[i][j] += a[i] * b[j];
        }
        __syncthreads();
    }

#pragma unroll
    for (int i = 0; i < 8; i++) {
        const int gm = m0 + ty * 8 + i;
        float* row = out + (size_t)gm * CDIM + n0 + tx * 8;
#pragma unroll
        for (int j4 = 0; j4 < 2; j4++) {
            float4 v;
            v.x = acc[i][j4 * 4 + 0] + bias[n0 + tx * 8 + j4 * 4 + 0];
            v.y = acc[i][j4 * 4 + 1] + bias[n0 + tx * 8 + j4 * 4 + 1];
            v.z = acc[i][j4 * 4 + 2] + bias[n0 + tx * 8 + j4 * 4 + 2];
            v.w = acc[i][j4 * 4 + 3] + bias[n0 + tx * 8 + j4 * 4 + 3];
            *(float4*)(row + j4 * 4) = v;
        }
    }
}

// ---------------------------------------------------------------------------
// Flash attention (causal, fp32). Block = one (b,h) x 64-query tile.
// 256 threads; thread (ty,tx) owns a 4x4 micro-tile. smem stride 65 vs bank
// conflicts; P buffer aliases K buffer (valid: sync between S-read and P-write).
// ---------------------------------------------------------------------------
#define AQ 64
#define AKT 64
#define ASTR 65
#define ATS (AQ * ASTR)

__global__ __launch_bounds__(256) void attn_kernel() {
    extern __shared__ float sm[];
    float* Qs = sm;
    float* Ks = sm + ATS;
    float* Vs = sm + 2 * ATS;
    float* Ps = Ks;  // alias

    const int t = threadIdx.x;
    const int qi = blockIdx.x;   // 0..31
    const int bh = blockIdx.y;   // 0..63
    const int q0 = qi * AQ;

    const float* Qg = g_Q + (size_t)bh * TLEN * HD;
    const float* Kg = g_K + (size_t)bh * TLEN * HD;
    const float* Vg = g_V + (size_t)bh * TLEN * HD;

    const int lrow = t >> 4, lc4 = (t & 15) * 4;

    // Load Q tile (once)
#pragma unroll
    for (int p = 0; p < 4; p++) {
        int r = lrow + p * 16;
        float4 v = *(const float4*)(Qg + (size_t)(q0 + r) * HD + lc4);
        Qs[r * ASTR + lc4 + 0] = v.x;
        Qs[r * ASTR + lc4 + 1] = v.y;
        Qs[r * ASTR + lc4 + 2] = v.z;
        Qs[r * ASTR + lc4 + 3] = v.w;
    }

    const int ty = t >> 4, tx = t & 15;
    const float scale = 0.125f;  // 1/sqrt(64)

    float m[4], l[4], o[4][4];
#pragma unroll
    for (int r = 0; r < 4; r++) {
        m[r] = -1e30f;
        l[r] = 0.f;
#pragma unroll
        for (int u = 0; u < 4; u++) o[r][u] = 0.f;
    }

    const int nkt = qi + 1;
    for (int kt = 0; kt < nkt; kt++) {
        const int k0 = kt * AKT;
        __syncthreads();  // prior P@V done before K/V overwrite
#pragma unroll
        for (int p = 0; p < 4; p++) {
            int r = lrow + p * 16;
            float4 kv = *(const float4*)(Kg + (size_t)(k0 + r) * HD + lc4);
            float4 vv = *(const float4*)(Vg + (size_t)(k0 + r) * HD + lc4);
            Ks[r * ASTR + lc4 + 0] = kv.x;
            Ks[r * ASTR + lc4 + 1] = kv.y;
            Ks[r * ASTR + lc4 + 2] = kv.z;
            Ks[r * ASTR + lc4 + 3] = kv.w;
            Vs[r * ASTR + lc4 + 0] = vv.x;
            Vs[r * ASTR + lc4 + 1] = vv.y;
            Vs[r * ASTR + lc4 + 2] = vv.z;
            Vs[r * ASTR + lc4 + 3] = vv.w;
        }
        __syncthreads();

        // S = scale * Q K^T   (4x4 per thread)
        float s[4][4];
#pragma unroll
        for (int r = 0; r < 4; r++)
#pragma unroll
            for (int u = 0; u < 4; u++) s[r][u] = 0.f;
#pragma unroll 8
        for (int d = 0; d < HD; d++) {
            float qr[4], kc[4];
#pragma unroll
            for (int r = 0; r < 4; r++) qr[r] = Qs[(ty * 4 + r) * ASTR + d];
#pragma unroll
            for (int u = 0; u < 4; u++) kc[u] = Ks[(tx * 4 + u) * ASTR + d];
#pragma unroll
            for (int r = 0; r < 4; r++)
#pragma unroll
                for (int u = 0; u < 4; u++) s[r][u] += qr[r] * kc[u];
        }

        const bool diag = (kt == qi);
#pragma unroll
        for (int r = 0; r < 4; r++) {
            const int gq = q0 + ty * 4 + r;
#pragma unroll
            for (int u = 0; u < 4; u++) {
                float sv = s[r][u] * scale;
                if (diag && (k0 + tx * 4 + u) > gq) sv = -1e30f;
                s[r][u] = sv;
            }
        }

        // Row max across 16-thread group (lanes 0-15 / 16-31 of a warp)
        float rmax[4];
#pragma unroll
        for (int r = 0; r < 4; r++) {
            float v = fmaxf(fmaxf(s[r][0], s[r][1]), fmaxf(s[r][2], s[r][3]));
#pragma unroll
            for (int off = 8; off >= 1; off >>= 1)
                v = fmaxf(v, __shfl_xor_sync(0xffffffffu, v, off));
            rmax[r] = v;
        }

        float alpha[4], rsum[4];
#pragma unroll
        for (int r = 0; r < 4; r++) {
            const float mn = fmaxf(m[r], rmax[r]);
            alpha[r] = __expf(m[r] - mn);
            m[r] = mn;
            float acc = 0.f;
#pragma unroll
            for (int u = 0; u < 4; u++) {
                const float p = __expf(s[r][u] - mn);
                s[r][u] = p;
                acc += p;
            }
#pragma unroll
            for (int off = 8; off >= 1; off >>= 1)
                acc += __shfl_xor_sync(0xffffffffu, acc, off);
            rsum[r] = acc;
        }
#pragma unroll
        for (int r = 0; r < 4; r++) {
            l[r] = l[r] * alpha[r] + rsum[r];
#pragma unroll
            for (int u = 0; u < 4; u++) o[r][u] *= alpha[r];
        }

        __syncthreads();  // everyone finished reading Ks before Ps(=Ks) write
#pragma unroll
        for (int r = 0; r < 4; r++)
#pragma unroll
            for (int u = 0; u < 4; u++)
                Ps[(ty * 4 + r) * ASTR + tx * 4 + u] = s[r][u];
        __syncthreads();

        // O += P @ V
#pragma unroll 8
        for (int kk = 0; kk < AKT; kk++) {
            float pr[4], vc[4];
#pragma unroll
            for (int r = 0; r < 4; r++) pr[r] = Ps[(ty * 4 + r) * ASTR + kk];
#pragma unroll
            for (int u = 0; u < 4; u++) vc[u] = Vs[kk * ASTR + tx * 4 + u];
#pragma unroll
            for (int r = 0; r < 4; r++)
#pragma unroll
                for (int u = 0; u < 4; u++) o[r][u] += pr[r] * vc[u];
        }
    }

    // Finalize: attn_out in [B,T,C]
    const int b = bh >> 4, h = bh & 15;
#pragma unroll
    for (int r = 0; r < 4; r++) {
        const float inv = 1.f / l[r];
        const int gq = q0 + ty * 4 + r;
        float* row = g_att + ((size_t)(b * TLEN + gq)) * CDIM + h * HD + tx * 4;
#pragma unroll
        for (int u = 0; u < 4; u++) row[u] = o[r][u] * inv;
    }
}

// ---------------------------------------------------------------------------
extern "C" void kernel_launch(void* const* d_in, const int* in_sizes, int n_in,
                              void* d_out, int out_size) {
    const float* x = (const float*)d_in[0];
    const float* W_qkv = (const float*)d_in[1];
    const float* b_qkv = (const float*)d_in[2];
    const float* W_proj = (const float*)d_in[3];
    const float* b_proj = (const float*)d_in[4];
    float* out = (float*)d_out;

    // Dynamic smem for attention (49,920 B > 48 KB static limit)
    const int attn_smem = 3 * ATS * (int)sizeof(float);
    cudaFuncSetAttribute(attn_kernel, cudaFuncAttributeMaxDynamicSharedMemorySize,
                         attn_smem);

    dim3 g1(N3 / GBN, BT / GBM);           // 24 x 64
    qkv_gemm<<<g1, 256>>>(x, W_qkv, b_qkv);

    dim3 g2(TLEN / AQ, BSZ * NH);          // 32 x 64
    attn_kernel<<<g2, 256, attn_smem>>>();

    dim3 g3(CDIM / GBN, BT / GBM);         // 8 x 64
    float* attn_ptr = nullptr;
    cudaGetSymbolAddress((void**)&attn_ptr, g_att);
    proj_gemm<<<g3, 256>>>(attn_ptr, W_proj, b_proj, out);
}

// round 3
// speedup vs baseline: 1.7404x; 1.7404x over previous
#include <cuda_runtime.h>
#include <cstdint>
#include <math.h>

#define BSZ 4
#define TLEN 2048
#define CDIM 1024
#define NH 16
#define HD 64
#define BT (BSZ * TLEN)      /* 8192 */
#define N3 (3 * CDIM)        /* 3072 */

// Scratch (allocation-free rule: __device__ globals)
__device__ float g_Q[BT * CDIM];      // [B,H,T,Dh]
__device__ float g_K[BT * CDIM];
__device__ float g_V[BT * CDIM];
__device__ float g_att[BT * CDIM];    // [B,T,C]
__device__ float g_WqkvT[N3 * CDIM];  // [3072,1024]  (W_qkv^T)
__device__ float g_WprojT[CDIM * CDIM];

// ---------------------------------------------------------------------------
// Portable tensor-core helpers (sm_80+ mma.sync — no 'a'-suffix features)
// ---------------------------------------------------------------------------
__device__ __forceinline__ uint32_t f2tf32(float x) {
    uint32_t u;
    asm("cvt.rna.tf32.f32 %0, %1;" : "=r"(u) : "f"(x));
    return u;
}

#define MMA_TF32(d, a, b)                                                        \
    asm volatile(                                                                \
        "mma.sync.aligned.m16n8k8.row.col.f32.tf32.tf32.f32 "                    \
        "{%0,%1,%2,%3}, {%4,%5,%6,%7}, {%8,%9}, {%0,%1,%2,%3};"                  \
        : "+f"((d)[0]), "+f"((d)[1]), "+f"((d)[2]), "+f"((d)[3])                 \
        : "r"((a)[0]), "r"((a)[1]), "r"((a)[2]), "r"((a)[3]),                    \
          "r"((b)[0]), "r"((b)[1]))

// ---------------------------------------------------------------------------
// One-shot weight transposes:  out[N,K] = in[K,N]^T
// ---------------------------------------------------------------------------
__global__ __launch_bounds__(256) void transpose32(const float* __restrict__ in,
                                                   float* __restrict__ out,
                                                   int R, int C) {
    __shared__ float tile[32][33];
    const int c0 = blockIdx.x * 32, r0 = blockIdx.y * 32;
    const int tx = threadIdx.x & 31, ty = threadIdx.x >> 5;
#pragma unroll
    for (int i = 0; i < 4; i++) {
        int r = ty + i * 8;
        tile[r][tx] = in[(size_t)(r0 + r) * C + c0 + tx];
    }
    __syncthreads();
#pragma unroll
    for (int i = 0; i < 4; i++) {
        int r = ty + i * 8;
        out[(size_t)(c0 + r) * R + r0 + tx] = tile[tx][r];
    }
}

// ---------------------------------------------------------------------------
// tf32 mma.sync GEMM: D[128x128] tile = A[m0:, :] * Bt[n0:, :]^T (+bias)
// 256 threads = 8 warps, warp grid 2x4, warp tile 64x32 (4x4 m16n8k8 frags).
// Smem stride 36 floats -> conflict-free fragment LDS.
// MODE 0: QKV epilogue scatter -> g_Q/g_K/g_V [B,H,T,Dh];  MODE 1: plain out.
// ---------------------------------------------------------------------------
#define SSTR 36

template <int MODE>
__global__ __launch_bounds__(256, 2)
void mm_tf32(const float* __restrict__ A, const float* __restrict__ Bt,
             const float* __restrict__ bias, float* __restrict__ out) {
    __shared__ uint32_t As[128 * SSTR];
    __shared__ uint32_t Bs[128 * SSTR];

    const int t = threadIdx.x;
    const int m0 = blockIdx.y * 128;
    const int n0 = blockIdx.x * 128;
    const int lane = t & 31, w = t >> 5;
    const int wr = w >> 2, wc = w & 3;      // warp grid 2 x 4

    float d[4][4][4];
#pragma unroll
    for (int i = 0; i < 4; i++)
#pragma unroll
        for (int j = 0; j < 4; j++)
#pragma unroll
            for (int e = 0; e < 4; e++) d[i][j][e] = 0.f;

    // Global staging: each thread does 4 float4 per matrix per chunk.
    const int gr = t >> 3;             // 0..31
    const int gc4 = (t & 7) * 4;       // 0,4,..,28
    const float* Ap = A + (size_t)(m0 + gr) * CDIM + gc4;
    const float* Bp = Bt + (size_t)(n0 + gr) * CDIM + gc4;

    // Fragment load bases
    const int ar = wr * 64 + (lane >> 2);   // A row
    const int ac = lane & 3;                // k sub-col
    const int br = wc * 32 + (lane >> 2);   // B row (= n)

    for (int k0 = 0; k0 < CDIM; k0 += 32) {
        __syncthreads();
#pragma unroll
        for (int p = 0; p < 4; p++) {
            const int row = gr + p * 32;
            float4 va = *(const float4*)(Ap + (size_t)(p * 32) * CDIM + k0);
            float4 vb = *(const float4*)(Bp + (size_t)(p * 32) * CDIM + k0);
            uint32_t* ad = &As[row * SSTR + gc4];
            uint32_t* bd = &Bs[row * SSTR + gc4];
            ad[0] = f2tf32(va.x); ad[1] = f2tf32(va.y);
            ad[2] = f2tf32(va.z); ad[3] = f2tf32(va.w);
            bd[0] = f2tf32(vb.x); bd[1] = f2tf32(vb.y);
            bd[2] = f2tf32(vb.z); bd[3] = f2tf32(vb.w);
        }
        __syncthreads();

#pragma unroll
        for (int ks = 0; ks < 4; ks++) {
            const int kk = ks * 8 + ac;
            uint32_t a[4][4], b[4][2];
#pragma unroll
            for (int i = 0; i < 4; i++) {
                const int r = (ar + i * 16) * SSTR;
                a[i][0] = As[r + kk];
                a[i][1] = As[r + 8 * SSTR + kk];
                a[i][2] = As[r + kk + 4];
                a[i][3] = As[r + 8 * SSTR + kk + 4];
            }
#pragma unroll
            for (int j = 0; j < 4; j++) {
                const int r = (br + j * 8) * SSTR;
                b[j][0] = Bs[r + kk];
                b[j][1] = Bs[r + kk + 4];
            }
#pragma unroll
            for (int i = 0; i < 4; i++)
#pragma unroll
                for (int j = 0; j < 4; j++) MMA_TF32(d[i][j], a[i], b[j]);
        }
    }

    // Epilogue. Frag layout: c0/c1 at (row=lane/4, col=2*(lane%4)+{0,1}),
    // c2/c3 at row+8.
    const int r0 = lane >> 2, c0 = (lane & 3) * 2;
#pragma unroll
    for (int i = 0; i < 4; i++) {
        const int gmA = m0 + wr * 64 + i * 16 + r0;
        const int gmB = gmA + 8;
#pragma unroll
        for (int j = 0; j < 4; j++) {
            const int gn = n0 + wc * 32 + j * 8 + c0;
            const float bx = bias[gn], by = bias[gn + 1];
            float2 vA = make_float2(d[i][j][0] + bx, d[i][j][1] + by);
            float2 vB = make_float2(d[i][j][2] + bx, d[i][j][3] + by);
            if (MODE == 0) {
                const int which = gn >> 10;
                const int c = gn & 1023;
                const int h = c >> 6, d0 = c & 63;
                float* base = (which == 0) ? g_Q : ((which == 1) ? g_K : g_V);
                const int bA = gmA >> 11, tA = gmA & 2047;
                const int bB = gmB >> 11, tB = gmB & 2047;
                *(float2*)(base + ((size_t)(bA * NH + h) * TLEN + tA) * HD + d0) = vA;
                *(float2*)(base + ((size_t)(bB * NH + h) * TLEN + tB) * HD + d0) = vB;
            } else {
                *(float2*)(out + (size_t)gmA * CDIM + gn) = vA;
                *(float2*)(out + (size_t)gmB * CDIM + gn) = vB;
            }
        }
    }
}

// ---------------------------------------------------------------------------
// Flash attention (causal, fp32 SIMT) — unchanged (passing, round-4 target)
// ---------------------------------------------------------------------------
#define AQ 64
#define AKT 64
#define ASTR 65
#define ATS (AQ * ASTR)

__global__ __launch_bounds__(256) void attn_kernel() {
    extern __shared__ float sm[];
    float* Qs = sm;
    float* Ks = sm + ATS;
    float* Vs = sm + 2 * ATS;
    float* Ps = Ks;  // alias

    const int t = threadIdx.x;
    const int qi = blockIdx.x;
    const int bh = blockIdx.y;
    const int q0 = qi * AQ;

    const float* Qg = g_Q + (size_t)bh * TLEN * HD;
    const float* Kg = g_K + (size_t)bh * TLEN * HD;
    const float* Vg = g_V + (size_t)bh * TLEN * HD;

    const int lrow = t >> 4, lc4 = (t & 15) * 4;

#pragma unroll
    for (int p = 0; p < 4; p++) {
        int rr = lrow + p * 16;
        float4 v = *(const float4*)(Qg + (size_t)(q0 + rr) * HD + lc4);
        Qs[rr * ASTR + lc4 + 0] = v.x;
        Qs[rr * ASTR + lc4 + 1] = v.y;
        Qs[rr * ASTR + lc4 + 2] = v.z;
        Qs[rr * ASTR + lc4 + 3] = v.w;
    }

    const int ty = t >> 4, tx = t & 15;
    const float scale = 0.125f;

    float m[4], l[4], o[4][4];
#pragma unroll
    for (int r = 0; r < 4; r++) {
        m[r] = -1e30f;
        l[r] = 0.f;
#pragma unroll
        for (int u = 0; u < 4; u++) o[r][u] = 0.f;
    }

    const int nkt = qi + 1;
    for (int kt = 0; kt < nkt; kt++) {
        const int k0 = kt * AKT;
        __syncthreads();
#pragma unroll
        for (int p = 0; p < 4; p++) {
            int rr = lrow + p * 16;
            float4 kv = *(const float4*)(Kg + (size_t)(k0 + rr) * HD + lc4);
            float4 vv = *(const float4*)(Vg + (size_t)(k0 + rr) * HD + lc4);
            Ks[rr * ASTR + lc4 + 0] = kv.x;
            Ks[rr * ASTR + lc4 + 1] = kv.y;
            Ks[rr * ASTR + lc4 + 2] = kv.z;
            Ks[rr * ASTR + lc4 + 3] = kv.w;
            Vs[rr * ASTR + lc4 + 0] = vv.x;
            Vs[rr * ASTR + lc4 + 1] = vv.y;
            Vs[rr * ASTR + lc4 + 2] = vv.z;
            Vs[rr * ASTR + lc4 + 3] = vv.w;
        }
        __syncthreads();

        float s[4][4];
#pragma unroll
        for (int r = 0; r < 4; r++)
#pragma unroll
            for (int u = 0; u < 4; u++) s[r][u] = 0.f;
#pragma unroll 8
        for (int dd = 0; dd < HD; dd++) {
            float qr[4], kc[4];
#pragma unroll
            for (int r = 0; r < 4; r++) qr[r] = Qs[(ty * 4 + r) * ASTR + dd];
#pragma unroll
            for (int u = 0; u < 4; u++) kc[u] = Ks[(tx * 4 + u) * ASTR + dd];
#pragma unroll
            for (int r = 0; r < 4; r++)
#pragma unroll
                for (int u = 0; u < 4; u++) s[r][u] += qr[r] * kc[u];
        }

        const bool diag = (kt == qi);
#pragma unroll
        for (int r = 0; r < 4; r++) {
            const int gq = q0 + ty * 4 + r;
#pragma unroll
            for (int u = 0; u < 4; u++) {
                float sv = s[r][u] * scale;
                if (diag && (k0 + tx * 4 + u) > gq) sv = -1e30f;
                s[r][u] = sv;
            }
        }

        float rmax[4];
#pragma unroll
        for (int r = 0; r < 4; r++) {
            float v = fmaxf(fmaxf(s[r][0], s[r][1]), fmaxf(s[r][2], s[r][3]));
#pragma unroll
            for (int off = 8; off >= 1; off >>= 1)
                v = fmaxf(v, __shfl_xor_sync(0xffffffffu, v, off));
            rmax[r] = v;
        }

        float alpha[4], rsum[4];
#pragma unroll
        for (int r = 0; r < 4; r++) {
            const float mn = fmaxf(m[r], rmax[r]);
            alpha[r] = __expf(m[r] - mn);
            m[r] = mn;
            float acc = 0.f;
#pragma unroll
            for (int u = 0; u < 4; u++) {
                const float p = __expf(s[r][u] - mn);
                s[r][u] = p;
                acc += p;
            }
#pragma unroll
            for (int off = 8; off >= 1; off >>= 1)
                acc += __shfl_xor_sync(0xffffffffu, acc, off);
            rsum[r] = acc;
        }
#pragma unroll
        for (int r = 0; r < 4; r++) {
            l[r] = l[r] * alpha[r] + rsum[r];
#pragma unroll
            for (int u = 0; u < 4; u++) o[r][u] *= alpha[r];
        }

        __syncthreads();
#pragma unroll
        for (int r = 0; r < 4; r++)
#pragma unroll
            for (int u = 0; u < 4; u++)
                Ps[(ty * 4 + r) * ASTR + tx * 4 + u] = s[r][u];
        __syncthreads();

#pragma unroll 8
        for (int kk = 0; kk < AKT; kk++) {
            float pr[4], vc[4];
#pragma unroll
            for (int r = 0; r < 4; r++) pr[r] = Ps[(ty * 4 + r) * ASTR + kk];
#pragma unroll
            for (int u = 0; u < 4; u++) vc[u] = Vs[kk * ASTR + tx * 4 + u];
#pragma unroll
            for (int r = 0; r < 4; r++)
#pragma unroll
                for (int u = 0; u < 4; u++) o[r][u] += pr[r] * vc[u];
        }
    }

    const int b = bh >> 4, h = bh & 15;
#pragma unroll
    for (int r = 0; r < 4; r++) {
        const float inv = 1.f / l[r];
        const int gq = q0 + ty * 4 + r;
        float* row = g_att + ((size_t)(b * TLEN + gq)) * CDIM + h * HD + tx * 4;
#pragma unroll
        for (int u = 0; u < 4; u++) row[u] = o[r][u] * inv;
    }
}

// ---------------------------------------------------------------------------
extern "C" void kernel_launch(void* const* d_in, const int* in_sizes, int n_in,
                              void* d_out, int out_size) {
    const float* x = (const float*)d_in[0];
    const float* W_qkv = (const float*)d_in[1];
    const float* b_qkv = (const float*)d_in[2];
    const float* W_proj = (const float*)d_in[3];
    const float* b_proj = (const float*)d_in[4];
    float* out = (float*)d_out;

    float *wqkvT = nullptr, *wprojT = nullptr, *attp = nullptr;
    cudaGetSymbolAddress((void**)&wqkvT, g_WqkvT);
    cudaGetSymbolAddress((void**)&wprojT, g_WprojT);
    cudaGetSymbolAddress((void**)&attp, g_att);

    const int attn_smem = 3 * ATS * (int)sizeof(float);
    cudaFuncSetAttribute(attn_kernel, cudaFuncAttributeMaxDynamicSharedMemorySize,
                         attn_smem);

    transpose32<<<dim3(N3 / 32, CDIM / 32), 256>>>(W_qkv, wqkvT, CDIM, N3);
    transpose32<<<dim3(CDIM / 32, CDIM / 32), 256>>>(W_proj, wprojT, CDIM, CDIM);

    mm_tf32<0><<<dim3(N3 / 128, BT / 128), 256>>>(x, wqkvT, b_qkv, nullptr);

    attn_kernel<<<dim3(TLEN / AQ, BSZ * NH), 256, attn_smem>>>();

    mm_tf32<1><<<dim3(CDIM / 128, BT / 128), 256>>>(attp, wprojT, b_proj, out);
}

// round 4
// speedup vs baseline: 3.1139x; 1.7891x over previous
#include <cuda_runtime.h>
#include <cstdint>
#include <math.h>

#define BSZ 4
#define TLEN 2048
#define CDIM 1024
#define NH 16
#define HD 64
#define BT (BSZ * TLEN)      /* 8192 */
#define N3 (3 * CDIM)        /* 3072 */

// Scratch (allocation-free rule: __device__ globals)
__device__ float g_Q[BT * CDIM];      // [B,H,T,Dh]
__device__ float g_K[BT * CDIM];
__device__ float g_V[BT * CDIM];
__device__ float g_att[BT * CDIM];    // [B,T,C]
__device__ float g_WqkvT[N3 * CDIM];  // [3072,1024]  (W_qkv^T)
__device__ float g_WprojT[CDIM * CDIM];

// ---------------------------------------------------------------------------
// Portable tensor-core helpers (sm_80+ mma.sync — no 'a'-suffix features)
// ---------------------------------------------------------------------------
__device__ __forceinline__ uint32_t f2tf32(float x) {
    uint32_t u;
    asm("cvt.rna.tf32.f32 %0, %1;" : "=r"(u) : "f"(x));
    return u;
}

#define MMA_TF32(d, a, b)                                                        \
    asm volatile(                                                                \
        "mma.sync.aligned.m16n8k8.row.col.f32.tf32.tf32.f32 "                    \
        "{%0,%1,%2,%3}, {%4,%5,%6,%7}, {%8,%9}, {%0,%1,%2,%3};"                  \
        : "+f"((d)[0]), "+f"((d)[1]), "+f"((d)[2]), "+f"((d)[3])                 \
        : "r"((a)[0]), "r"((a)[1]), "r"((a)[2]), "r"((a)[3]),                    \
          "r"((b)[0]), "r"((b)[1]))

// ---------------------------------------------------------------------------
// One-shot weight transposes:  out[N,K] = in[K,N]^T
// ---------------------------------------------------------------------------
__global__ __launch_bounds__(256) void transpose32(const float* __restrict__ in,
                                                   float* __restrict__ out,
                                                   int R, int C) {
    __shared__ float tile[32][33];
    const int c0 = blockIdx.x * 32, r0 = blockIdx.y * 32;
    const int tx = threadIdx.x & 31, ty = threadIdx.x >> 5;
#pragma unroll
    for (int i = 0; i < 4; i++) {
        int r = ty + i * 8;
        tile[r][tx] = in[(size_t)(r0 + r) * C + c0 + tx];
    }
    __syncthreads();
#pragma unroll
    for (int i = 0; i < 4; i++) {
        int r = ty + i * 8;
        out[(size_t)(c0 + r) * R + r0 + tx] = tile[tx][r];
    }
}

// ---------------------------------------------------------------------------
// tf32 mma.sync GEMM (unchanged from round 3, passing)
// ---------------------------------------------------------------------------
#define SSTR 36

template <int MODE>
__global__ __launch_bounds__(256, 2)
void mm_tf32(const float* __restrict__ A, const float* __restrict__ Bt,
             const float* __restrict__ bias, float* __restrict__ out) {
    __shared__ uint32_t As[128 * SSTR];
    __shared__ uint32_t Bs[128 * SSTR];

    const int t = threadIdx.x;
    const int m0 = blockIdx.y * 128;
    const int n0 = blockIdx.x * 128;
    const int lane = t & 31, w = t >> 5;
    const int wr = w >> 2, wc = w & 3;

    float d[4][4][4];
#pragma unroll
    for (int i = 0; i < 4; i++)
#pragma unroll
        for (int j = 0; j < 4; j++)
#pragma unroll
            for (int e = 0; e < 4; e++) d[i][j][e] = 0.f;

    const int gr = t >> 3;
    const int gc4 = (t & 7) * 4;
    const float* Ap = A + (size_t)(m0 + gr) * CDIM + gc4;
    const float* Bp = Bt + (size_t)(n0 + gr) * CDIM + gc4;

    const int ar = wr * 64 + (lane >> 2);
    const int ac = lane & 3;
    const int br = wc * 32 + (lane >> 2);

    for (int k0 = 0; k0 < CDIM; k0 += 32) {
        __syncthreads();
#pragma unroll
        for (int p = 0; p < 4; p++) {
            const int row = gr + p * 32;
            float4 va = *(const float4*)(Ap + (size_t)(p * 32) * CDIM + k0);
            float4 vb = *(const float4*)(Bp + (size_t)(p * 32) * CDIM + k0);
            uint32_t* ad = &As[row * SSTR + gc4];
            uint32_t* bd = &Bs[row * SSTR + gc4];
            ad[0] = f2tf32(va.x); ad[1] = f2tf32(va.y);
            ad[2] = f2tf32(va.z); ad[3] = f2tf32(va.w);
            bd[0] = f2tf32(vb.x); bd[1] = f2tf32(vb.y);
            bd[2] = f2tf32(vb.z); bd[3] = f2tf32(vb.w);
        }
        __syncthreads();

#pragma unroll
        for (int ks = 0; ks < 4; ks++) {
            const int kk = ks * 8 + ac;
            uint32_t a[4][4], b[4][2];
#pragma unroll
            for (int i = 0; i < 4; i++) {
                const int r = (ar + i * 16) * SSTR;
                a[i][0] = As[r + kk];
                a[i][1] = As[r + 8 * SSTR + kk];
                a[i][2] = As[r + kk + 4];
                a[i][3] = As[r + 8 * SSTR + kk + 4];
            }
#pragma unroll
            for (int j = 0; j < 4; j++) {
                const int r = (br + j * 8) * SSTR;
                b[j][0] = Bs[r + kk];
                b[j][1] = Bs[r + kk + 4];
            }
#pragma unroll
            for (int i = 0; i < 4; i++)
#pragma unroll
                for (int j = 0; j < 4; j++) MMA_TF32(d[i][j], a[i], b[j]);
        }
    }

    const int r0 = lane >> 2, c0 = (lane & 3) * 2;
#pragma unroll
    for (int i = 0; i < 4; i++) {
        const int gmA = m0 + wr * 64 + i * 16 + r0;
        const int gmB = gmA + 8;
#pragma unroll
        for (int j = 0; j < 4; j++) {
            const int gn = n0 + wc * 32 + j * 8 + c0;
            const float bx = bias[gn], by = bias[gn + 1];
            float2 vA = make_float2(d[i][j][0] + bx, d[i][j][1] + by);
            float2 vB = make_float2(d[i][j][2] + bx, d[i][j][3] + by);
            if (MODE == 0) {
                const int which = gn >> 10;
                const int c = gn & 1023;
                const int h = c >> 6, d0 = c & 63;
                float* base = (which == 0) ? g_Q : ((which == 1) ? g_K : g_V);
                const int bA = gmA >> 11, tA = gmA & 2047;
                const int bB = gmB >> 11, tB = gmB & 2047;
                *(float2*)(base + ((size_t)(bA * NH + h) * TLEN + tA) * HD + d0) = vA;
                *(float2*)(base + ((size_t)(bB * NH + h) * TLEN + tB) * HD + d0) = vB;
            } else {
                *(float2*)(out + (size_t)gmA * CDIM + gn) = vA;
                *(float2*)(out + (size_t)gmB * CDIM + gn) = vB;
            }
        }
    }
}

// ---------------------------------------------------------------------------
// Tensor-core flash attention (causal, tf32 mma.sync).
// Block = 128 threads (4 warps), Q tile 64, K tile 64. Warp w owns q rows
// [w*16, w*16+16). S and O live in MMA fragments; softmax in registers with
// shfl_xor(1,2) row reductions. P repacked via smem (aliases K buffer).
// V stored transposed in smem (B operand of m16n8k8 is col-major).
// ---------------------------------------------------------------------------
#define SA 68
#define ATTN_SMEM (3 * 64 * SA * 4)

__global__ __launch_bounds__(128) void attn_mma() {
    extern __shared__ uint32_t smw[];
    uint32_t* Qs = smw;               // 64 x SA
    uint32_t* Ks = smw + 64 * SA;     // 64 x SA, aliased as Ps
    uint32_t* Vt = smw + 2 * 64 * SA; // 64 x SA  (Vt[d][key])

    const int t = threadIdx.x;
    const int lane = t & 31, w = t >> 5;
    const int qi = blockIdx.x;        // q tile
    const int bh = blockIdx.y;        // (b,h)
    const int q0 = qi * 64;

    const float* Qg = g_Q + (size_t)bh * TLEN * HD;
    const float* Kg = g_K + (size_t)bh * TLEN * HD;
    const float* Vg = g_V + (size_t)bh * TLEN * HD;

    // Load Q tile once, scale folded in (1/sqrt(64) = 0.125)
    for (int i = t; i < 64 * 16; i += 128) {
        const int row = i >> 4, c4 = (i & 15) * 4;
        float4 v = *(const float4*)(Qg + (size_t)(q0 + row) * HD + c4);
        uint4 u;
        u.x = f2tf32(v.x * 0.125f);
        u.y = f2tf32(v.y * 0.125f);
        u.z = f2tf32(v.z * 0.125f);
        u.w = f2tf32(v.w * 0.125f);
        *(uint4*)&Qs[row * SA + c4] = u;
    }

    const int r0w = w * 16 + (lane >> 2);   // warp-local q row (first of pair)
    const int abase = r0w * SA;
    const int lk = lane & 3;

    float o[8][4];
#pragma unroll
    for (int j = 0; j < 8; j++)
#pragma unroll
        for (int e = 0; e < 4; e++) o[j][e] = 0.f;
    float m0 = -1e30f, m1 = -1e30f, l0 = 0.f, l1 = 0.f;

    for (int kt = 0; kt <= qi; kt++) {
        const int k0 = kt * 64;
        __syncthreads();  // Q visible (iter 0); Ks/Vt free of prior readers
        for (int i = t; i < 64 * 16; i += 128) {
            const int row = i >> 4, c4 = (i & 15) * 4;
            float4 kv = *(const float4*)(Kg + (size_t)(k0 + row) * HD + c4);
            uint4 u;
            u.x = f2tf32(kv.x); u.y = f2tf32(kv.y);
            u.z = f2tf32(kv.z); u.w = f2tf32(kv.w);
            *(uint4*)&Ks[row * SA + c4] = u;
            float4 vv = *(const float4*)(Vg + (size_t)(k0 + row) * HD + c4);
            Vt[(c4 + 0) * SA + row] = f2tf32(vv.x);
            Vt[(c4 + 1) * SA + row] = f2tf32(vv.y);
            Vt[(c4 + 2) * SA + row] = f2tf32(vv.z);
            Vt[(c4 + 3) * SA + row] = f2tf32(vv.w);
        }
        __syncthreads();

        // S = (Q*scale) @ K^T
        float s[8][4];
#pragma unroll
        for (int j = 0; j < 8; j++)
#pragma unroll
            for (int e = 0; e < 4; e++) s[j][e] = 0.f;
#pragma unroll
        for (int ks = 0; ks < 8; ks++) {
            const int kk = ks * 8 + lk;
            uint32_t a[4];
            a[0] = Qs[abase + kk];
            a[1] = Qs[abase + 8 * SA + kk];
            a[2] = Qs[abase + kk + 4];
            a[3] = Qs[abase + 8 * SA + kk + 4];
#pragma unroll
            for (int j = 0; j < 8; j++) {
                const int r = (j * 8 + (lane >> 2)) * SA;
                uint32_t b[2];
                b[0] = Ks[r + kk];
                b[1] = Ks[r + kk + 4];
                MMA_TF32(s[j], a, b);
            }
        }

        // Causal mask (diagonal tile only; uniform branch)
        if (kt == qi) {
            const int gr0 = q0 + r0w, gr1 = gr0 + 8;
#pragma unroll
            for (int j = 0; j < 8; j++) {
                const int c = k0 + j * 8 + 2 * lk;
                if (c > gr0) s[j][0] = -1e30f;
                if (c + 1 > gr0) s[j][1] = -1e30f;
                if (c > gr1) s[j][2] = -1e30f;
                if (c + 1 > gr1) s[j][3] = -1e30f;
            }
        }

        // Online softmax: rows r0w (c0,c1) and r0w+8 (c2,c3)
        float tm0 = -1e30f, tm1 = -1e30f;
#pragma unroll
        for (int j = 0; j < 8; j++) {
            tm0 = fmaxf(tm0, fmaxf(s[j][0], s[j][1]));
            tm1 = fmaxf(tm1, fmaxf(s[j][2], s[j][3]));
        }
        tm0 = fmaxf(tm0, __shfl_xor_sync(0xffffffffu, tm0, 1));
        tm0 = fmaxf(tm0, __shfl_xor_sync(0xffffffffu, tm0, 2));
        tm1 = fmaxf(tm1, __shfl_xor_sync(0xffffffffu, tm1, 1));
        tm1 = fmaxf(tm1, __shfl_xor_sync(0xffffffffu, tm1, 2));

        const float mn0 = fmaxf(m0, tm0), mn1 = fmaxf(m1, tm1);
        const float al0 = __expf(m0 - mn0), al1 = __expf(m1 - mn1);
        m0 = mn0; m1 = mn1;

        float rs0 = 0.f, rs1 = 0.f;
#pragma unroll
        for (int j = 0; j < 8; j++) {
            s[j][0] = __expf(s[j][0] - mn0); rs0 += s[j][0];
            s[j][1] = __expf(s[j][1] - mn0); rs0 += s[j][1];
            s[j][2] = __expf(s[j][2] - mn1); rs1 += s[j][2];
            s[j][3] = __expf(s[j][3] - mn1); rs1 += s[j][3];
        }
        rs0 += __shfl_xor_sync(0xffffffffu, rs0, 1);
        rs0 += __shfl_xor_sync(0xffffffffu, rs0, 2);
        rs1 += __shfl_xor_sync(0xffffffffu, rs1, 1);
        rs1 += __shfl_xor_sync(0xffffffffu, rs1, 2);
        l0 = l0 * al0 + rs0;
        l1 = l1 * al1 + rs1;
#pragma unroll
        for (int j = 0; j < 8; j++) {
            o[j][0] *= al0; o[j][1] *= al0;
            o[j][2] *= al1; o[j][3] *= al1;
        }

        __syncthreads();  // all warps done reading Ks before P overwrite
        uint32_t* Ps = Ks;
        const int pc = 2 * lk;
#pragma unroll
        for (int j = 0; j < 8; j++) {
            uint2 u0 = make_uint2(f2tf32(s[j][0]), f2tf32(s[j][1]));
            *(uint2*)&Ps[abase + j * 8 + pc] = u0;
            uint2 u1 = make_uint2(f2tf32(s[j][2]), f2tf32(s[j][3]));
            *(uint2*)&Ps[abase + 8 * SA + j * 8 + pc] = u1;
        }
        __syncwarp();

        // O += P @ V   (A = Ps rows of this warp, B = Vt col-major)
#pragma unroll
        for (int ks = 0; ks < 8; ks++) {
            const int kk = ks * 8 + lk;
            uint32_t a[4];
            a[0] = Ps[abase + kk];
            a[1] = Ps[abase + 8 * SA + kk];
            a[2] = Ps[abase + kk + 4];
            a[3] = Ps[abase + 8 * SA + kk + 4];
#pragma unroll
            for (int j = 0; j < 8; j++) {
                const int r = (j * 8 + (lane >> 2)) * SA;
                uint32_t b[2];
                b[0] = Vt[r + kk];
                b[1] = Vt[r + kk + 4];
                MMA_TF32(o[j], a, b);
            }
        }
    }

    // Epilogue -> g_att [B,T,C]
    const float inv0 = 1.f / l0, inv1 = 1.f / l1;
    const int b = bh >> 4, h = bh & 15;
    const int gr0 = q0 + r0w, gr1 = gr0 + 8;
    float* o0 = g_att + ((size_t)(b * TLEN + gr0)) * CDIM + h * HD;
    float* o1 = g_att + ((size_t)(b * TLEN + gr1)) * CDIM + h * HD;
#pragma unroll
    for (int j = 0; j < 8; j++) {
        const int c = j * 8 + 2 * lk;
        *(float2*)(o0 + c) = make_float2(o[j][0] * inv0, o[j][1] * inv0);
        *(float2*)(o1 + c) = make_float2(o[j][2] * inv1, o[j][3] * inv1);
    }
}

// ---------------------------------------------------------------------------
extern "C" void kernel_launch(void* const* d_in, const int* in_sizes, int n_in,
                              void* d_out, int out_size) {
    const float* x = (const float*)d_in[0];
    const float* W_qkv = (const float*)d_in[1];
    const float* b_qkv = (const float*)d_in[2];
    const float* W_proj = (const float*)d_in[3];
    const float* b_proj = (const float*)d_in[4];
    float* out = (float*)d_out;

    float *wqkvT = nullptr, *wprojT = nullptr, *attp = nullptr;
    cudaGetSymbolAddress((void**)&wqkvT, g_WqkvT);
    cudaGetSymbolAddress((void**)&wprojT, g_WprojT);
    cudaGetSymbolAddress((void**)&attp, g_att);

    cudaFuncSetAttribute(attn_mma, cudaFuncAttributeMaxDynamicSharedMemorySize,
                         ATTN_SMEM);

    transpose32<<<dim3(N3 / 32, CDIM / 32), 256>>>(W_qkv, wqkvT, CDIM, N3);
    transpose32<<<dim3(CDIM / 32, CDIM / 32), 256>>>(W_proj, wprojT, CDIM, CDIM);

    mm_tf32<0><<<dim3(N3 / 128, BT / 128), 256>>>(x, wqkvT, b_qkv, nullptr);

    attn_mma<<<dim3(TLEN / 64, BSZ * NH), 128, ATTN_SMEM>>>();

    mm_tf32<1><<<dim3(CDIM / 128, BT / 128), 256>>>(attp, wprojT, b_proj, out);
}